// round 11
// baseline (speedup 1.0000x reference)
#include <cuda_runtime.h>
#include <cstdint>

// SecConv2d on GB300 (validated model):
//   int32 inputs (x 32x64x56x56, w 64x64x3x3, b 64), values < 2^16
//   expected output = conv with int32 wraparound (mod 2^32), stored as f32.
// Compute sum mod 2^32 with u32 IMADs; store (float)(int32)(sum + bias).
//
// R10 profile: L1=63% (6 scalar LDGs/thread per (c,kh)), fma=36%, occ=20%.
// R11: x staged in smem (vector LDS), 3 CTAs/SM, float4 epilogue.

#define NTHREADS 224        // 2 kgroups x (8 rows x 14 colgroups)
#define TK 8                // k-channels per thread
#define TP 4                // pixels per thread
#define KT 16               // k-channels per CTA
#define ROWS 8              // output rows per CTA
#define CCH 4               // channels staged per chunk
#define NCHUNK (64/CCH)     // 16
#define XSTR 68             // x smem row stride (words): 16B-aligned, low conflicts
#define WSH_ELEMS (576*KT)  // 9216 u32 = 36KB
#define XS_ELEMS (CCH*10*XSTR) // 2720 u32 = 10.6KB  (total 46.6KB static)

__global__ void __launch_bounds__(NTHREADS, 3)
secconv2d_u32(const int* __restrict__ x,
              const int* __restrict__ w,
              const int* __restrict__ bias,
              float* __restrict__ out)
{
    __shared__ unsigned int wsh[WSH_ELEMS];   // [r=0..575][kk=0..15]
    __shared__ unsigned int xs[XS_ELEMS];     // [c_local][j=0..9][col=0..57]

    const int tid = threadIdx.x;
    const int kt  = blockIdx.x;     // 0..3  -> 16 output channels
    const int rt  = blockIdx.y;     // 0..6  -> 8 output rows
    const int n   = blockIdx.z;     // 0..31
    const int r0  = rt * ROWS;

    // Stage all weights for this 16-channel tile: w flat = k*576 + r.
    for (int e = tid; e < WSH_ELEMS; e += NTHREADS) {
        int kk = e / 576;
        int r  = e - kk * 576;
        wsh[r * KT + kk] = (unsigned int)__ldg(&w[(kt * KT + kk) * 576 + r]);
    }

    const int kg    = tid / 112;              // 0..1
    const int lane  = tid - kg * 112;         // 0..111
    const int row   = lane / 14;              // 0..7
    const int col4  = (lane - row * 14) * TP; // 0,4,...,52
    const int orow  = r0 + row;
    const int kbase = kt * KT + kg * TK;

    const int* xn = x + n * 200704;

    unsigned int acc[TK][TP];
    #pragma unroll
    for (int a = 0; a < TK; ++a)
        #pragma unroll
        for (int b = 0; b < TP; ++b) acc[a][b] = 0u;

    const int xbase0 = row * XSTR + col4;     // fixed per-thread x smem base

    for (int chunk = 0; chunk < NCHUNK; ++chunk) {
        __syncthreads();   // prior compute done (and weights staged, iter 0)

        // Stage x chunk: CCH channels x 10 input rows x 58 cols (zero-padded).
        #pragma unroll 1
        for (int e = tid; e < CCH * 10 * 58; e += NTHREADS) {
            int cl  = e / 580;
            int rem = e - cl * 580;
            int j   = rem / 58;
            int col = rem - j * 58;
            int ir  = r0 - 1 + j;
            int ic  = col - 1;
            unsigned int v = 0u;
            if (((unsigned)ir < 56u) && ((unsigned)ic < 56u))
                v = (unsigned int)__ldg(xn + (chunk * CCH + cl) * 3136 + ir * 56 + ic);
            xs[(cl * 10 + j) * XSTR + col] = v;
        }
        __syncthreads();

        const int wchunk = chunk * (CCH * 9) * KT + kg * TK;  // wsh base this chunk

        #pragma unroll
        for (int cc = 0; cc < CCH; ++cc) {
            #pragma unroll
            for (int kh = 0; kh < 3; ++kh) {
                // 6 x taps via one LDS.128 + one LDS.64 (aligned)
                const int xb = (cc * 10 + kh) * XSTR + xbase0;
                const uint4 xa = *(const uint4*)&xs[xb];
                const uint2 xc = *(const uint2*)&xs[xb + 4];
                const unsigned int xr[6] = {xa.x, xa.y, xa.z, xa.w, xc.x, xc.y};

                #pragma unroll
                for (int kw = 0; kw < 3; ++kw) {
                    const int q = wchunk + (cc * 9 + kh * 3 + kw) * KT;
                    const uint4 w0 = *(const uint4*)&wsh[q];
                    const uint4 w1 = *(const uint4*)&wsh[q + 4];
                    const unsigned int wv[TK] = {w0.x, w0.y, w0.z, w0.w,
                                                 w1.x, w1.y, w1.z, w1.w};
                    #pragma unroll
                    for (int a = 0; a < TK; ++a)
                        #pragma unroll
                        for (int b = 0; b < TP; ++b)
                            acc[a][b] += xr[kw + b] * wv[a];   // u32 IMAD
                }
            }
        }
    }

    // Epilogue: wrap-to-int32, convert to f32, vectorized stores.
    float* outn = out + n * 200704;
    #pragma unroll
    for (int a = 0; a < TK; ++a) {
        const int k = kbase + a;
        const unsigned int bv = (unsigned int)__ldg(&bias[k]);
        float4 o;
        o.x = (float)(int)(acc[a][0] + bv);
        o.y = (float)(int)(acc[a][1] + bv);
        o.z = (float)(int)(acc[a][2] + bv);
        o.w = (float)(int)(acc[a][3] + bv);
        *(float4*)&outn[k * 3136 + orow * 56 + col4] = o;
    }
}

extern "C" void kernel_launch(void* const* d_in, const int* in_sizes, int n_in,
                              void* d_out, int out_size)
{
    // Bind by size ranking: largest = x, smallest = bias, remaining = weight.
    int ix = 0, ib = 0;
    for (int i = 1; i < n_in; ++i) {
        if (in_sizes[i] > in_sizes[ix]) ix = i;
        if (in_sizes[i] < in_sizes[ib]) ib = i;
    }
    int iw = 0;
    for (int i = 0; i < n_in; ++i)
        if (i != ix && i != ib) { iw = i; break; }

    const int* x = (const int*)d_in[ix];
    const int* w = (const int*)d_in[iw];
    const int* b = (const int*)d_in[ib];
    float* out   = (float*)d_out;

    dim3 grid(4, 7, 32);   // 16k x 8rows x 32 batch = 896 CTAs, zero waste
    secconv2d_u32<<<grid, NTHREADS>>>(x, w, b, out);
}

// round 12
// speedup vs baseline: 1.4118x; 1.4118x over previous
#include <cuda_runtime.h>
#include <cstdint>

// SecConv2d on GB300 (validated model):
//   int32 inputs (x 32x64x56x56, w 64x64x3x3, b 64), values < 2^16
//   expected output = conv with int32 wraparound (mod 2^32), stored as f32.
// Compute sum mod 2^32 with u32 IMADs; store (float)(int32)(sum + bias).
//
// R10 (246us): LDG-tap version, issue/latency-bound (occ 20%, issue 55%).
// R11 (330us): smem-staged x — REGRESSED (32 barrier ping-pongs, no overlap).
// R12: R10 structure + vectorized taps (uint4 + 2 scalars, 18->9 LDG/c)
//      + 3 CTAs/SM occupancy + float4 epilogue. No extra barriers.

#define NTHREADS 224        // 2 kgroups x (8 rows x 14 colgroups)
#define TK 8                // k-channels per thread
#define TP 4                // pixels per thread
#define KT 16               // k-channels per CTA
#define ROWS 8              // output rows per CTA
#define WSH_ELEMS (576*KT)  // 9216 u32 = 36KB static smem

__global__ void __launch_bounds__(NTHREADS, 3)
secconv2d_u32(const int* __restrict__ x,
              const int* __restrict__ w,
              const int* __restrict__ bias,
              float* __restrict__ out)
{
    __shared__ unsigned int wsh[WSH_ELEMS];   // [r=0..575][kk=0..15]

    const int tid = threadIdx.x;
    const int kt  = blockIdx.x;     // 0..3  -> 16 output channels
    const int rt  = blockIdx.y;     // 0..6  -> 8 output rows
    const int n   = blockIdx.z;     // 0..31

    // Stage weights for this 16-channel tile: w flat = k*576 + r.
    for (int e = tid; e < WSH_ELEMS; e += NTHREADS) {
        int kk = e / 576;
        int r  = e - kk * 576;
        wsh[r * KT + kk] = (unsigned int)__ldg(&w[(kt * KT + kk) * 576 + r]);
    }
    __syncthreads();

    const int kg    = tid / 112;              // 0..1
    const int lane  = tid - kg * 112;         // 0..111
    const int row   = lane / 14;              // 0..7
    const int col4  = (lane - row * 14) * TP; // 0,4,...,52
    const int orow  = rt * ROWS + row;        // 0..55 (always valid)
    const int kbase = kt * KT + kg * TK;

    const bool has_l = (col4 > 0);            // left boundary tap exists
    const bool has_r = (col4 < 52);           // right boundary tap exists

    // per-thread x pointer at (channel 0, row orow, col col4)
    const int* xp = x + n * 200704 + orow * 56 + col4;

    unsigned int acc[TK][TP];
    #pragma unroll
    for (int a = 0; a < TK; ++a)
        #pragma unroll
        for (int b = 0; b < TP; ++b) acc[a][b] = 0u;

    #pragma unroll 2
    for (int c = 0; c < 64; ++c) {
        #pragma unroll
        for (int kh = 0; kh < 3; ++kh) {
            const int ir = orow - 1 + kh;              // input row
            const bool okr = ((unsigned)ir < 56u);
            const int* xrow = xp + (kh - 1) * 56;      // &x[c][ir][col4], 16B-aligned

            // 6 taps: [col4-1 .. col4+4] via 1x LDG.128 + 2 boundary scalars
            uint4 xa = okr ? __ldg((const uint4*)xrow)
                           : make_uint4(0u, 0u, 0u, 0u);
            unsigned int xl = (okr && has_l) ? (unsigned int)__ldg(xrow - 1) : 0u;
            unsigned int xrgt = (okr && has_r) ? (unsigned int)__ldg(xrow + 4) : 0u;
            const unsigned int xr[6] = {xl, xa.x, xa.y, xa.z, xa.w, xrgt};

            #pragma unroll
            for (int kw = 0; kw < 3; ++kw) {
                const int q = (c * 9 + kh * 3 + kw) * KT + kg * TK;
                const uint4 w0 = *(const uint4*)&wsh[q];       // broadcast LDS.128
                const uint4 w1 = *(const uint4*)&wsh[q + 4];
                const unsigned int wv[TK] = {w0.x, w0.y, w0.z, w0.w,
                                             w1.x, w1.y, w1.z, w1.w};
                #pragma unroll
                for (int a = 0; a < TK; ++a)
                    #pragma unroll
                    for (int b = 0; b < TP; ++b)
                        acc[a][b] += xr[kw + b] * wv[a];       // u32 IMAD (mod 2^32)
            }
        }
        xp += 3136;   // next channel
    }

    // Epilogue: wrap to int32, convert to f32, vectorized stores.
    float* outp = out + n * 200704 + orow * 56 + col4;
    #pragma unroll
    for (int a = 0; a < TK; ++a) {
        const int k = kbase + a;
        const unsigned int bv = (unsigned int)__ldg(&bias[k]);
        float4 o;
        o.x = (float)(int)(acc[a][0] + bv);
        o.y = (float)(int)(acc[a][1] + bv);
        o.z = (float)(int)(acc[a][2] + bv);
        o.w = (float)(int)(acc[a][3] + bv);
        *(float4*)&outp[k * 3136] = o;
    }
}

extern "C" void kernel_launch(void* const* d_in, const int* in_sizes, int n_in,
                              void* d_out, int out_size)
{
    // Bind by size ranking: largest = x, smallest = bias, remaining = weight.
    int ix = 0, ib = 0;
    for (int i = 1; i < n_in; ++i) {
        if (in_sizes[i] > in_sizes[ix]) ix = i;
        if (in_sizes[i] < in_sizes[ib]) ib = i;
    }
    int iw = 0;
    for (int i = 0; i < n_in; ++i)
        if (i != ix && i != ib) { iw = i; break; }

    const int* x = (const int*)d_in[ix];
    const int* w = (const int*)d_in[iw];
    const int* b = (const int*)d_in[ib];
    float* out   = (float*)d_out;

    dim3 grid(4, 7, 32);   // 16k x 8rows x 32 batch = 896 CTAs, zero waste
    secconv2d_u32<<<grid, NTHREADS>>>(x, w, b, out);
}